// round 6
// baseline (speedup 1.0000x reference)
#include <cuda_runtime.h>
#include <cuda_bf16.h>
#include <cstdint>

#define NP 16384
#define NG 16384
#define NB 2048                  // x-buckets
#define XMIN (-5.5f)
#define XSPAN 11.0f
#define XW (XSPAN / (float)NB)   // bucket width
#define INV_W ((float)NB / XSPAN)
#define FLT_BIG 3.402823466e38f
#define NB_COMBINE 64

// ---------------------------------------------------------------------------
// Device-global scratch (no allocation allowed).
// hist_* must be zero at the start of each replay: statically zero-initialized,
// and re-zeroed inside k_scan immediately after being consumed.
// Everything else is fully rebuilt every replay.
// ---------------------------------------------------------------------------
__device__ int    hist_p[NB], hist_g[NB];
__device__ int    cstart_p[NB + 1], cstart_g[NB + 1];
__device__ int    cursor_p[NB], cursor_g[NB];
__device__ float4 spt[NP], sgt[NG];       // bucket-sorted points (x,y,z,0)
__device__ int    orig_p[NP], orig_g[NG]; // sorted slot -> original index
__device__ float  minp[NP], ming[NG];     // per-original-index min d2
__device__ float  g_part[NB_COMBINE][4];
__device__ unsigned int g_ctr;

__device__ __forceinline__ int bucket_of(float x) {
    int b = (int)((x - XMIN) * INV_W);
    return min(max(b, 0), NB - 1);
}

// ---------------------------------------------------------------------------
// K1: histogram of x-buckets for both clouds (32768 threads)
// ---------------------------------------------------------------------------
__global__ void k_hist(const float* __restrict__ pp, const float* __restrict__ gp) {
    int i = blockIdx.x * blockDim.x + threadIdx.x;
    if (i < NP) {
        atomicAdd(&hist_p[bucket_of(pp[3 * i])], 1);
    } else {
        int j = i - NP;
        atomicAdd(&hist_g[bucket_of(gp[3 * j])], 1);
    }
}

// ---------------------------------------------------------------------------
// K2: exclusive scan of both histograms (single block, 1024 threads).
// Writes cstart (NB+1 entries) and cursor; zeroes hist for the next replay.
// ---------------------------------------------------------------------------
__device__ __forceinline__ void scan_one(int* hist, int* cstart, int* cursor, int total) {
    __shared__ int wsum[32];
    const int tid = threadIdx.x;
    const int lane = tid & 31;
    const int w = tid >> 5;

    int v0 = hist[2 * tid];
    int v1 = hist[2 * tid + 1];
    int s = v0 + v1;

    // warp-inclusive scan of per-thread sums
    int incl = s;
#pragma unroll
    for (int o = 1; o < 32; o <<= 1) {
        int n = __shfl_up_sync(0xffffffffu, incl, o);
        if (lane >= o) incl += n;
    }
    if (lane == 31) wsum[w] = incl;
    __syncthreads();
    if (w == 0) {
        int t2 = wsum[lane];
        int inc2 = t2;
#pragma unroll
        for (int o = 1; o < 32; o <<= 1) {
            int n = __shfl_up_sync(0xffffffffu, inc2, o);
            if (lane >= o) inc2 += n;
        }
        wsum[lane] = inc2 - t2;   // exclusive warp offsets
    }
    __syncthreads();

    int base = wsum[w] + incl - s;        // exclusive prefix of element 2*tid
    cstart[2 * tid] = base;
    cstart[2 * tid + 1] = base + v0;
    cursor[2 * tid] = base;
    cursor[2 * tid + 1] = base + v0;
    hist[2 * tid] = 0;                    // reset for next replay
    hist[2 * tid + 1] = 0;
    if (tid == 1023) cstart[NB] = total;
    __syncthreads();                      // wsum reuse safety
}

__global__ void k_scan() {
    scan_one(hist_p, cstart_p, cursor_p, NP);
    scan_one(hist_g, cstart_g, cursor_g, NG);
}

// ---------------------------------------------------------------------------
// K3: scatter points into bucket-sorted arrays (32768 threads).
// Within-bucket order is nondeterministic (atomic), but mins are
// order-independent so the final result is deterministic.
// ---------------------------------------------------------------------------
__global__ void k_scatter(const float* __restrict__ pp, const float* __restrict__ gp) {
    int i = blockIdx.x * blockDim.x + threadIdx.x;
    if (i < NP) {
        float x = pp[3 * i], y = pp[3 * i + 1], z = pp[3 * i + 2];
        int pos = atomicAdd(&cursor_p[bucket_of(x)], 1);
        spt[pos] = make_float4(x, y, z, 0.f);
        orig_p[pos] = i;
    } else {
        int j = i - NP;
        float x = gp[3 * j], y = gp[3 * j + 1], z = gp[3 * j + 2];
        int pos = atomicAdd(&cursor_g[bucket_of(x)], 1);
        sgt[pos] = make_float4(x, y, z, 0.f);
        orig_g[pos] = j;
    }
}

// ---------------------------------------------------------------------------
// K4: NN queries. 65536 threads: 2 lanes per query (side 0 = own bucket +
// left sweep, side 1 = own bucket + right sweep), combined via shfl_xor.
// First 32768 threads: pred->gt. Last 32768: gt->pred.
// Exactness of the sweep cutoff: for a left-side bucket b, every element has
// x < right_edge(b) (clamping only pushes outliers outward-consistently), so
// dx = px - right_edge(b) lower-bounds |px - gx| and dx^2 >= best proves all
// remaining left elements are >= best (best only shrinks).
// ---------------------------------------------------------------------------
__global__ __launch_bounds__(256) void k_query() {
    const int t = blockIdx.x * blockDim.x + threadIdx.x;
    const int half = t >> 15;          // 0: pred queries, 1: gt queries
    const int u = t & 32767;
    const int q = u >> 1;              // sorted query slot
    const int side = u & 1;

    const float4* __restrict__ T  = half ? spt : sgt;           // target cloud
    const int*    __restrict__ cs = half ? cstart_p : cstart_g;
    const float4 p = half ? sgt[q] : spt[q];
    const float px = p.x, py = p.y, pz = p.z;

    const int bq = bucket_of(px);
    float best = FLT_BIG;

    // own bucket (both sides scan it; duplicate work is tiny)
    {
        const int s = cs[bq], e = cs[bq + 1];
        for (int k = s; k < e; k++) {
            float4 g = T[k];
            float dx = px - g.x, dy = py - g.y, dz = pz - g.z;
            float d = fmaf(dx, dx, fmaf(dy, dy, dz * dz));
            best = fminf(best, d);
        }
    }

    if (side == 0) {
        // sweep left
        for (int b = bq - 1; b >= 0; b--) {
            float dx = px - (XMIN + (float)(b + 1) * XW);   // >= 0
            if (dx * dx >= best) break;
            const int s = cs[b], e = cs[b + 1];
            for (int k = s; k < e; k++) {
                float4 g = T[k];
                float ddx = px - g.x, dy = py - g.y, dz = pz - g.z;
                float d = fmaf(ddx, ddx, fmaf(dy, dy, dz * dz));
                best = fminf(best, d);
            }
        }
    } else {
        // sweep right
        for (int b = bq + 1; b < NB; b++) {
            float dx = (XMIN + (float)b * XW) - px;         // >= 0
            if (dx * dx >= best) break;
            const int s = cs[b], e = cs[b + 1];
            for (int k = s; k < e; k++) {
                float4 g = T[k];
                float ddx = px - g.x, dy = py - g.y, dz = pz - g.z;
                float d = fmaf(ddx, ddx, fmaf(dy, dy, dz * dz));
                best = fminf(best, d);
            }
        }
    }

    // combine lane pair (2q, 2q+1 are in the same warp: 32768 % 32 == 0)
    float other = __shfl_xor_sync(0xffffffffu, best, 1);
    best = fminf(best, other);
    if (side == 0) {
        if (half) ming[orig_g[q]] = best;
        else      minp[orig_p[q]] = best;
    }
}

// ---------------------------------------------------------------------------
// K5: weighted partial sums (64 blocks) + last-block final combine.
// Deterministic fixed-order sums. Resets g_ctr for next replay.
// ---------------------------------------------------------------------------
__global__ __launch_bounds__(256, 1)
void k_combine(const float* __restrict__ wp, const float* __restrict__ wg,
               float* __restrict__ out) {
    __shared__ float sh[4][8];
    __shared__ unsigned int s_ticket;
    const int b = blockIdx.x;
    const int tid = threadIdx.x;
    const int lane = tid & 31;
    const int wid = tid >> 5;
    const int i = b * 256 + tid;

    float mp = minp[i];
    float mg = ming[i];
    float w1 = wp[i], w2 = wg[i];
    float a0 = w1 * mp, a1 = w1, a2 = w2 * mg, a3 = w2;

#pragma unroll
    for (int o = 16; o > 0; o >>= 1) {
        a0 += __shfl_down_sync(0xffffffffu, a0, o);
        a1 += __shfl_down_sync(0xffffffffu, a1, o);
        a2 += __shfl_down_sync(0xffffffffu, a2, o);
        a3 += __shfl_down_sync(0xffffffffu, a3, o);
    }
    if (lane == 0) { sh[0][wid] = a0; sh[1][wid] = a1; sh[2][wid] = a2; sh[3][wid] = a3; }
    __syncthreads();
    if (tid == 0) {
        float t0 = 0.f, t1 = 0.f, t2 = 0.f, t3 = 0.f;
#pragma unroll
        for (int w = 0; w < 8; w++) { t0 += sh[0][w]; t1 += sh[1][w]; t2 += sh[2][w]; t3 += sh[3][w]; }
        g_part[b][0] = t0; g_part[b][1] = t1; g_part[b][2] = t2; g_part[b][3] = t3;
        __threadfence();
        s_ticket = atomicAdd(&g_ctr, 1u);
    }
    __syncthreads();

    if (s_ticket == NB_COMBINE - 1) {     // last-arriving block finalizes
        __threadfence();
        if (tid < NB_COMBINE) {
            volatile float (*part)[4] = g_part;
            float p0 = part[tid][0], p1 = part[tid][1];
            float p2 = part[tid][2], p3 = part[tid][3];
#pragma unroll
            for (int o = 16; o > 0; o >>= 1) {
                p0 += __shfl_down_sync(0xffffffffu, p0, o);
                p1 += __shfl_down_sync(0xffffffffu, p1, o);
                p2 += __shfl_down_sync(0xffffffffu, p2, o);
                p3 += __shfl_down_sync(0xffffffffu, p3, o);
            }
            if (lane == 0) {
                sh[0][wid] = p0; sh[1][wid] = p1; sh[2][wid] = p2; sh[3][wid] = p3;
            }
        }
        __syncthreads();
        if (tid == 0) {
            float s0 = sh[0][0] + sh[0][1];
            float s1 = sh[1][0] + sh[1][1];
            float s2 = sh[2][0] + sh[2][1];
            float s3 = sh[3][0] + sh[3][1];
            out[0] = s0 / fmaxf(s1, 1e-9f) + s2 / fmaxf(s3, 1e-9f);
            g_ctr = 0u;   // reset for next replay
        }
    }
}

// ---------------------------------------------------------------------------
extern "C" void kernel_launch(void* const* d_in, const int* in_sizes, int n_in,
                              void* d_out, int out_size) {
    const float* pred = (const float*)d_in[0];   // (P,3)
    const float* gt   = (const float*)d_in[1];   // (G,3)
    const float* wp   = (const float*)d_in[2];   // (P,)
    const float* wg   = (const float*)d_in[3];   // (G,)
    float* out = (float*)d_out;

    k_hist<<<(NP + NG) / 256, 256>>>(pred, gt);
    k_scan<<<1, 1024>>>();
    k_scatter<<<(NP + NG) / 256, 256>>>(pred, gt);
    k_query<<<(2 * (NP + NG)) / 256, 256>>>();
    k_combine<<<NB_COMBINE, 256>>>(wp, wg, out);
}

// round 8
// speedup vs baseline: 3.4191x; 3.4191x over previous
#include <cuda_runtime.h>
#include <cuda_bf16.h>
#include <cstdint>

#define NP 16384
#define NG 16384
#define NB 2048                  // x-buckets (anchor lookup only)
#define XMIN (-5.5f)
#define XSPAN 11.0f
#define INV_W ((float)NB / XSPAN)
#define FLT_BIG 3.402823466e38f
#define NB_COMBINE 64
#define NQWARPS 1024             // 32768 queries / 32

// ---------------------------------------------------------------------------
// Device-global scratch. hist_* zero at replay start (static init + re-zeroed
// in k_scan after use). Everything else fully rebuilt every replay.
// ---------------------------------------------------------------------------
__device__ int    hist_p[NB], hist_g[NB];
__device__ int    cstart_p[NB + 1], cstart_g[NB + 1];
__device__ int    cursor_p[NB], cursor_g[NB];
__device__ float4 spt[NP], sgt[NG];       // x-sorted points (x,y,z,|pt|^2)
__device__ int    orig_p[NP], orig_g[NG];
__device__ float  minp[NP], ming[NG];
__device__ float  g_part[NB_COMBINE][4];
__device__ unsigned int g_ctr;

__device__ __forceinline__ int bucket_of(float x) {
    int b = (int)((x - XMIN) * INV_W);
    return min(max(b, 0), NB - 1);
}

// ---------------------------------------------------------------------------
// K1: bucket histograms
// ---------------------------------------------------------------------------
__global__ void k_hist(const float* __restrict__ pp, const float* __restrict__ gp) {
    int i = blockIdx.x * blockDim.x + threadIdx.x;
    if (i < NP) atomicAdd(&hist_p[bucket_of(pp[3 * i])], 1);
    else        atomicAdd(&hist_g[bucket_of(gp[3 * (i - NP)])], 1);
}

// ---------------------------------------------------------------------------
// K2: exclusive scan (1 block, 1024 threads); resets hist for next replay.
// ---------------------------------------------------------------------------
__device__ __forceinline__ void scan_one(int* hist, int* cstart, int* cursor, int total) {
    __shared__ int wsum[32];
    const int tid = threadIdx.x, lane = tid & 31, w = tid >> 5;
    int v0 = hist[2 * tid], v1 = hist[2 * tid + 1];
    int s = v0 + v1, incl = s;
#pragma unroll
    for (int o = 1; o < 32; o <<= 1) {
        int n = __shfl_up_sync(0xffffffffu, incl, o);
        if (lane >= o) incl += n;
    }
    if (lane == 31) wsum[w] = incl;
    __syncthreads();
    if (w == 0) {
        int t2 = wsum[lane], inc2 = t2;
#pragma unroll
        for (int o = 1; o < 32; o <<= 1) {
            int n = __shfl_up_sync(0xffffffffu, inc2, o);
            if (lane >= o) inc2 += n;
        }
        wsum[lane] = inc2 - t2;
    }
    __syncthreads();
    int base = wsum[w] + incl - s;
    cstart[2 * tid] = base;       cstart[2 * tid + 1] = base + v0;
    cursor[2 * tid] = base;       cursor[2 * tid + 1] = base + v0;
    hist[2 * tid] = 0;            hist[2 * tid + 1] = 0;
    if (tid == 1023) cstart[NB] = total;
    __syncthreads();
}

__global__ void k_scan() {
    scan_one(hist_p, cstart_p, cursor_p, NP);
    scan_one(hist_g, cstart_g, cursor_g, NG);
}

// ---------------------------------------------------------------------------
// K3: scatter into x-sorted order (within-bucket order irrelevant: mins).
// ---------------------------------------------------------------------------
__global__ void k_scatter(const float* __restrict__ pp, const float* __restrict__ gp) {
    int i = blockIdx.x * blockDim.x + threadIdx.x;
    if (i < NP) {
        float x = pp[3 * i], y = pp[3 * i + 1], z = pp[3 * i + 2];
        int pos = atomicAdd(&cursor_p[bucket_of(x)], 1);
        spt[pos] = make_float4(x, y, z, x * x + y * y + z * z);
        orig_p[pos] = i;
    } else {
        int j = i - NP;
        float x = gp[3 * j], y = gp[3 * j + 1], z = gp[3 * j + 2];
        int pos = atomicAdd(&cursor_g[bucket_of(x)], 1);
        sgt[pos] = make_float4(x, y, z, x * x + y * y + z * z);
        orig_g[pos] = j;
    }
}

// ---------------------------------------------------------------------------
// K4: warp-cooperative NN. One warp = 32 consecutive sorted queries sharing a
// candidate window on the (x-sorted) target array. Window grows in 32-wide
// chunks (left/right of an anchor); all lanes evaluate every staged candidate
// against their own query. Exact stop: remaining left candidates have
// x <= xL, so max(px-xL,0)^2 >= best_d2 (voted across the warp) proves them
// out; symmetric on the right. t-space trick: t = -2 p.g + |g|^2; d2 = t+|p|^2.
// ---------------------------------------------------------------------------
__global__ __launch_bounds__(256)
void k_query() {
    __shared__ float4 sh[8][32];
    const int lane = threadIdx.x & 31;
    const int wlocal = threadIdx.x >> 5;
    const int gw = blockIdx.x * 8 + wlocal;         // 0..NQWARPS-1
    const int half = (gw >= NQWARPS / 2);           // 0: pred queries, 1: gt
    const int q = (gw & (NQWARPS / 2 - 1)) * 32 + lane;

    const float4* __restrict__ T  = half ? spt : sgt;         // target cloud
    const int*    __restrict__ cs = half ? cstart_p : cstart_g;
    const float4 p = half ? sgt[q] : spt[q];
    const float px = p.x, pq = p.w;
    const float qx = -2.0f * p.x, qy = -2.0f * p.y, qz = -2.0f * p.z;

    // warp-uniform anchor from lane 0's query
    const float px0 = __shfl_sync(0xffffffffu, px, 0);
    int R = cs[bucket_of(px0)];                     // next right chunk start
    int L = R;                                      // left boundary (exclusive)

    float b0 = FLT_BIG, b1 = FLT_BIG, b2 = FLT_BIG, b3 = FLT_BIG; // t-space
    float xL = 0.f, xR = 0.f;
    bool goL = (L > 0), goR = (R < NG);
    bool vL = false, vR = false;                    // chunk processed this iter

    while (goL || goR) {
        // ---- right chunk [R, R+32) ----
        vR = false;
        if (goR) {
            int idx = R + lane;
            float4 g = (idx < NG) ? T[idx] : make_float4(0.f, 0.f, 0.f, FLT_BIG);
            xR = __shfl_sync(0xffffffffu, g.x, 31);
            sh[wlocal][lane] = g;
            __syncwarp();
#pragma unroll
            for (int k = 0; k < 32; k += 4) {
                float4 c0 = sh[wlocal][k + 0];
                float4 c1 = sh[wlocal][k + 1];
                float4 c2 = sh[wlocal][k + 2];
                float4 c3 = sh[wlocal][k + 3];
                float t0 = fmaf(qx, c0.x, fmaf(qy, c0.y, fmaf(qz, c0.z, c0.w)));
                float t1 = fmaf(qx, c1.x, fmaf(qy, c1.y, fmaf(qz, c1.z, c1.w)));
                float t2 = fmaf(qx, c2.x, fmaf(qy, c2.y, fmaf(qz, c2.z, c2.w)));
                float t3 = fmaf(qx, c3.x, fmaf(qy, c3.y, fmaf(qz, c3.z, c3.w)));
                b0 = fminf(b0, t0); b1 = fminf(b1, t1);
                b2 = fminf(b2, t2); b3 = fminf(b3, t3);
            }
            __syncwarp();
            if (R + 32 >= NG) goR = false; else vR = true;
            R += 32;
        }
        // ---- left chunk [L-32, L) ----
        vL = false;
        if (goL) {
            int base = L - 32;
            int idx = base + lane;
            float4 g = (idx >= 0) ? T[idx] : make_float4(0.f, 0.f, 0.f, FLT_BIG);
            xL = __shfl_sync(0xffffffffu, g.x, 0);
            sh[wlocal][lane] = g;
            __syncwarp();
#pragma unroll
            for (int k = 0; k < 32; k += 4) {
                float4 c0 = sh[wlocal][k + 0];
                float4 c1 = sh[wlocal][k + 1];
                float4 c2 = sh[wlocal][k + 2];
                float4 c3 = sh[wlocal][k + 3];
                float t0 = fmaf(qx, c0.x, fmaf(qy, c0.y, fmaf(qz, c0.z, c0.w)));
                float t1 = fmaf(qx, c1.x, fmaf(qy, c1.y, fmaf(qz, c1.z, c1.w)));
                float t2 = fmaf(qx, c2.x, fmaf(qy, c2.y, fmaf(qz, c2.z, c2.w)));
                float t3 = fmaf(qx, c3.x, fmaf(qy, c3.y, fmaf(qz, c3.z, c3.w)));
                b0 = fminf(b0, t0); b1 = fminf(b1, t1);
                b2 = fminf(b2, t2); b3 = fminf(b3, t3);
            }
            __syncwarp();
            if (base <= 0) goL = false; else vL = true;
            L = base;
        }
        // ---- termination votes (warp-uniform results) ----
        float bd = fminf(fminf(b0, b1), fminf(b2, b3)) + pq;   // best d2 so far
        if (vR) {
            float dx = fmaxf(xR - px, 0.0f);
            if (__all_sync(0xffffffffu, dx * dx >= bd)) goR = false;
        }
        if (vL) {
            float dx = fmaxf(px - xL, 0.0f);
            if (__all_sync(0xffffffffu, dx * dx >= bd)) goL = false;
        }
    }

    float best = fmaxf(fminf(fminf(b0, b1), fminf(b2, b3)) + pq, 0.0f);
    if (half) ming[orig_g[q]] = best;
    else      minp[orig_p[q]] = best;
}

// ---------------------------------------------------------------------------
// K5: weighted partial sums + last-block final combine (deterministic).
// ---------------------------------------------------------------------------
__global__ __launch_bounds__(256, 1)
void k_combine(const float* __restrict__ wp, const float* __restrict__ wg,
               float* __restrict__ out) {
    __shared__ float sh[4][8];
    __shared__ unsigned int s_ticket;
    const int b = blockIdx.x, tid = threadIdx.x;
    const int lane = tid & 31, wid = tid >> 5;
    const int i = b * 256 + tid;

    float mp = minp[i], mg = ming[i];
    float w1 = wp[i], w2 = wg[i];
    float a0 = w1 * mp, a1 = w1, a2 = w2 * mg, a3 = w2;
#pragma unroll
    for (int o = 16; o > 0; o >>= 1) {
        a0 += __shfl_down_sync(0xffffffffu, a0, o);
        a1 += __shfl_down_sync(0xffffffffu, a1, o);
        a2 += __shfl_down_sync(0xffffffffu, a2, o);
        a3 += __shfl_down_sync(0xffffffffu, a3, o);
    }
    if (lane == 0) { sh[0][wid] = a0; sh[1][wid] = a1; sh[2][wid] = a2; sh[3][wid] = a3; }
    __syncthreads();
    if (tid == 0) {
        float t0 = 0.f, t1 = 0.f, t2 = 0.f, t3 = 0.f;
#pragma unroll
        for (int w = 0; w < 8; w++) { t0 += sh[0][w]; t1 += sh[1][w]; t2 += sh[2][w]; t3 += sh[3][w]; }
        g_part[b][0] = t0; g_part[b][1] = t1; g_part[b][2] = t2; g_part[b][3] = t3;
        __threadfence();
        s_ticket = atomicAdd(&g_ctr, 1u);
    }
    __syncthreads();

    if (s_ticket == NB_COMBINE - 1) {
        __threadfence();
        if (tid < NB_COMBINE) {
            volatile float (*part)[4] = g_part;
            float p0 = part[tid][0], p1 = part[tid][1];
            float p2 = part[tid][2], p3 = part[tid][3];
#pragma unroll
            for (int o = 16; o > 0; o >>= 1) {
                p0 += __shfl_down_sync(0xffffffffu, p0, o);
                p1 += __shfl_down_sync(0xffffffffu, p1, o);
                p2 += __shfl_down_sync(0xffffffffu, p2, o);
                p3 += __shfl_down_sync(0xffffffffu, p3, o);
            }
            if (lane == 0) { sh[0][wid] = p0; sh[1][wid] = p1; sh[2][wid] = p2; sh[3][wid] = p3; }
        }
        __syncthreads();
        if (tid == 0) {
            float s0 = sh[0][0] + sh[0][1];
            float s1 = sh[1][0] + sh[1][1];
            float s2 = sh[2][0] + sh[2][1];
            float s3 = sh[3][0] + sh[3][1];
            out[0] = s0 / fmaxf(s1, 1e-9f) + s2 / fmaxf(s3, 1e-9f);
            g_ctr = 0u;
        }
    }
}

// ---------------------------------------------------------------------------
extern "C" void kernel_launch(void* const* d_in, const int* in_sizes, int n_in,
                              void* d_out, int out_size) {
    const float* pred = (const float*)d_in[0];
    const float* gt   = (const float*)d_in[1];
    const float* wp   = (const float*)d_in[2];
    const float* wg   = (const float*)d_in[3];
    float* out = (float*)d_out;

    k_hist<<<(NP + NG) / 256, 256>>>(pred, gt);
    k_scan<<<1, 1024>>>();
    k_scatter<<<(NP + NG) / 256, 256>>>(pred, gt);
    k_query<<<NQWARPS / 8, 256>>>();
    k_combine<<<NB_COMBINE, 256>>>(wp, wg, out);
}

// round 9
// speedup vs baseline: 4.7788x; 1.3977x over previous
#include <cuda_runtime.h>
#include <cuda_bf16.h>
#include <cstdint>

#define NP 16384
#define NG 16384
#define NB 2048                  // x-buckets (anchor lookup only)
#define XMIN (-5.5f)
#define XSPAN 11.0f
#define INV_W ((float)NB / XSPAN)
#define FLT_BIG 3.402823466e38f
#define INF_BITS 0x7f800000u
#define NB_COMBINE 64
#define CH 16                    // fixed chunks per side (512 candidates)

// ---------------------------------------------------------------------------
// Device-global scratch. hist_* and g_key_* must be zero at replay start:
// statically zero-initialized, and re-zeroed by the consuming kernel.
// ---------------------------------------------------------------------------
__device__ int    hist_p[NB], hist_g[NB];
__device__ int    cstart_p[NB + 1], cstart_g[NB + 1];
__device__ int    cursor_p[NB], cursor_g[NB];
__device__ float4 spt[NP], sgt[NG];       // x-sorted (x,y,z,|pt|^2)
__device__ int    orig_p[NP], orig_g[NG];
__device__ unsigned int g_key_pred[NP];   // key = INF_BITS - bits(min d2); 0 == +inf
__device__ unsigned int g_key_gt[NG];
__device__ float  g_part[NB_COMBINE][4];
__device__ unsigned int g_ctr;

__device__ __forceinline__ int bucket_of(float x) {
    int b = (int)((x - XMIN) * INV_W);
    return min(max(b, 0), NB - 1);
}

// ---------------------------------------------------------------------------
// K1: bucket histograms
// ---------------------------------------------------------------------------
__global__ void k_hist(const float* __restrict__ pp, const float* __restrict__ gp) {
    int i = blockIdx.x * blockDim.x + threadIdx.x;
    if (i < NP) atomicAdd(&hist_p[bucket_of(pp[3 * i])], 1);
    else        atomicAdd(&hist_g[bucket_of(gp[3 * (i - NP)])], 1);
}

// ---------------------------------------------------------------------------
// K2: exclusive scan, one block per cloud; resets hist for next replay.
// ---------------------------------------------------------------------------
__device__ __forceinline__ void scan_one(int* hist, int* cstart, int* cursor, int total) {
    __shared__ int wsum[32];
    const int tid = threadIdx.x, lane = tid & 31, w = tid >> 5;
    int v0 = hist[2 * tid], v1 = hist[2 * tid + 1];
    int s = v0 + v1, incl = s;
#pragma unroll
    for (int o = 1; o < 32; o <<= 1) {
        int n = __shfl_up_sync(0xffffffffu, incl, o);
        if (lane >= o) incl += n;
    }
    if (lane == 31) wsum[w] = incl;
    __syncthreads();
    if (w == 0) {
        int t2 = wsum[lane], inc2 = t2;
#pragma unroll
        for (int o = 1; o < 32; o <<= 1) {
            int n = __shfl_up_sync(0xffffffffu, inc2, o);
            if (lane >= o) inc2 += n;
        }
        wsum[lane] = inc2 - t2;
    }
    __syncthreads();
    int base = wsum[w] + incl - s;
    cstart[2 * tid] = base;       cstart[2 * tid + 1] = base + v0;
    cursor[2 * tid] = base;       cursor[2 * tid + 1] = base + v0;
    hist[2 * tid] = 0;            hist[2 * tid + 1] = 0;
    if (tid == 1023) cstart[NB] = total;
}

__global__ void k_scan() {
    if (blockIdx.x == 0) scan_one(hist_p, cstart_p, cursor_p, NP);
    else                 scan_one(hist_g, cstart_g, cursor_g, NG);
}

// ---------------------------------------------------------------------------
// K3: scatter into x-sorted order (within-bucket order irrelevant: mins).
// ---------------------------------------------------------------------------
__global__ void k_scatter(const float* __restrict__ pp, const float* __restrict__ gp) {
    int i = blockIdx.x * blockDim.x + threadIdx.x;
    if (i < NP) {
        float x = pp[3 * i], y = pp[3 * i + 1], z = pp[3 * i + 2];
        int pos = atomicAdd(&cursor_p[bucket_of(x)], 1);
        spt[pos] = make_float4(x, y, z, x * x + y * y + z * z);
        orig_p[pos] = i;
    } else {
        int j = i - NP;
        float x = gp[3 * j], y = gp[3 * j + 1], z = gp[3 * j + 2];
        int pos = atomicAdd(&cursor_g[bucket_of(x)], 1);
        sgt[pos] = make_float4(x, y, z, x * x + y * y + z * z);
        orig_g[pos] = j;
    }
}

// ---------------------------------------------------------------------------
// K4: warp-cooperative NN, one DIRECTION per warp (2048 warps total).
//   gw = warp id; side = gw&1 (0: right incl. anchor, 1: left of anchor);
//   group = gw>>1; half = group>=512 (0: pred queries, 1: gt queries);
//   queries = 32 consecutive x-sorted slots.
// Phase 1: CH fixed chunks, software-pipelined LDG prefetch, smem staging,
//          NO votes (dense). Phase 2: rare adaptive extension with votes.
// Exactness: skipped candidates on a side have dx^2 >= side-best >= final
// combined min, so they cannot change the answer. OOB sentinels have
// w=FLT_BIG (never win) and x=+-1e30 (terminate the sweep).
// t-space: t = -2 p.g + |g|^2, d2 = t + |p|^2, clamp at the very end.
// ---------------------------------------------------------------------------
__global__ __launch_bounds__(256)
void k_query() {
    __shared__ float4 sh[8][2][32];
    const int lane = threadIdx.x & 31;
    const int wl = threadIdx.x >> 5;
    const int gw = blockIdx.x * 8 + wl;             // 0..2047
    const int side = gw & 1;                        // 0: right, 1: left
    const int group = gw >> 1;                      // 0..1023
    const int half = (group >= 512);                // 0: pred, 1: gt
    const int q = (group & 511) * 32 + lane;

    const float4* __restrict__ T  = half ? spt : sgt;
    const int*    __restrict__ cs = half ? cstart_p : cstart_g;
    const float4 p = half ? sgt[q] : spt[q];
    const float px = p.x, pq = p.w;
    const float qx = -2.0f * p.x, qy = -2.0f * p.y, qz = -2.0f * p.z;

    const float px0 = __shfl_sync(0xffffffffu, px, 0);
    const int anchor = cs[bucket_of(px0)];

    float b0 = FLT_BIG, b1 = FLT_BIG, b2 = FLT_BIG, b3 = FLT_BIG;
    float xedge;                                   // outermost x examined

    // chunk base for chunk index c on this side
    //   right: anchor + 32*c        left: anchor - 32*(c+1)
    // -------- phase 1: CH pipelined chunks --------
    {
        int base0 = side ? (anchor - 32) : anchor;
        int step  = side ? -32 : 32;
        // prefetch chunk 0
        int idx = base0 + lane;
        float4 nxt;
        if (idx >= 0 && idx < NG) nxt = T[idx];
        else nxt = make_float4(side ? -1e30f : 1e30f, 0.f, 0.f, FLT_BIG);

#pragma unroll 4
        for (int c = 0; c < CH; c++) {
            float4 cur = nxt;
            // prefetch chunk c+1 (always; harmless OOB -> sentinel)
            if (c + 1 < CH) {
                int nidx = base0 + (c + 1) * step + lane;
                if (nidx >= 0 && nidx < NG) nxt = T[nidx];
                else nxt = make_float4(side ? -1e30f : 1e30f, 0.f, 0.f, FLT_BIG);
            }
            xedge = __shfl_sync(0xffffffffu, cur.x, side ? 0 : 31);
            sh[wl][c & 1][lane] = cur;
            __syncwarp();
#pragma unroll
            for (int k = 0; k < 32; k += 4) {
                float4 c0 = sh[wl][c & 1][k + 0];
                float4 c1 = sh[wl][c & 1][k + 1];
                float4 c2 = sh[wl][c & 1][k + 2];
                float4 c3 = sh[wl][c & 1][k + 3];
                float t0 = fmaf(qx, c0.x, fmaf(qy, c0.y, fmaf(qz, c0.z, c0.w)));
                float t1 = fmaf(qx, c1.x, fmaf(qy, c1.y, fmaf(qz, c1.z, c1.w)));
                float t2 = fmaf(qx, c2.x, fmaf(qy, c2.y, fmaf(qz, c2.z, c2.w)));
                float t3 = fmaf(qx, c3.x, fmaf(qy, c3.y, fmaf(qz, c3.z, c3.w)));
                b0 = fminf(b0, t0); b1 = fminf(b1, t1);
                b2 = fminf(b2, t2); b3 = fminf(b3, t3);
            }
            __syncwarp();
        }
    }

    // -------- phase 2: rare adaptive extension --------
    {
        int nextb = side ? (anchor - 32 * (CH + 1)) : (anchor + 32 * CH);
        while (true) {
            float bd = fminf(fminf(b0, b1), fminf(b2, b3)) + pq;
            float dx = side ? fmaxf(px - xedge, 0.0f) : fmaxf(xedge - px, 0.0f);
            if (__all_sync(0xffffffffu, dx * dx >= bd)) break;
            if (side ? (nextb + 32 <= 0) : (nextb >= NG)) break;

            int idx = nextb + lane;
            float4 g;
            if (idx >= 0 && idx < NG) g = T[idx];
            else g = make_float4(side ? -1e30f : 1e30f, 0.f, 0.f, FLT_BIG);
            xedge = __shfl_sync(0xffffffffu, g.x, side ? 0 : 31);
            __syncwarp();
            sh[wl][0][lane] = g;
            __syncwarp();
#pragma unroll
            for (int k = 0; k < 32; k += 4) {
                float4 c0 = sh[wl][0][k + 0];
                float4 c1 = sh[wl][0][k + 1];
                float4 c2 = sh[wl][0][k + 2];
                float4 c3 = sh[wl][0][k + 3];
                float t0 = fmaf(qx, c0.x, fmaf(qy, c0.y, fmaf(qz, c0.z, c0.w)));
                float t1 = fmaf(qx, c1.x, fmaf(qy, c1.y, fmaf(qz, c1.z, c1.w)));
                float t2 = fmaf(qx, c2.x, fmaf(qy, c2.y, fmaf(qz, c2.z, c2.w)));
                float t3 = fmaf(qx, c3.x, fmaf(qy, c3.y, fmaf(qz, c3.z, c3.w)));
                b0 = fminf(b0, t0); b1 = fminf(b1, t1);
                b2 = fminf(b2, t2); b3 = fminf(b3, t3);
            }
            __syncwarp();
            nextb += side ? -32 : 32;
        }
    }

    float best = fmaxf(fminf(fminf(b0, b1), fminf(b2, b3)) + pq, 0.0f);
    unsigned key = INF_BITS - __float_as_uint(best);
    if (half) atomicMax(&g_key_gt[orig_g[q]], key);
    else      atomicMax(&g_key_pred[orig_p[q]], key);
}

// ---------------------------------------------------------------------------
// K5: weighted partial sums + last-block final combine (deterministic).
// Decodes keys; resets keys + counter for next replay.
// ---------------------------------------------------------------------------
__global__ __launch_bounds__(256, 1)
void k_combine(const float* __restrict__ wp, const float* __restrict__ wg,
               float* __restrict__ out) {
    __shared__ float sh[4][8];
    __shared__ unsigned int s_ticket;
    const int b = blockIdx.x, tid = threadIdx.x;
    const int lane = tid & 31, wid = tid >> 5;
    const int i = b * 256 + tid;

    unsigned kp = g_key_pred[i];
    unsigned kg = g_key_gt[i];
    g_key_pred[i] = 0u;
    g_key_gt[i]   = 0u;
    float mp = __uint_as_float(INF_BITS - kp);
    float mg = __uint_as_float(INF_BITS - kg);
    float w1 = wp[i], w2 = wg[i];
    float a0 = w1 * mp, a1 = w1, a2 = w2 * mg, a3 = w2;
#pragma unroll
    for (int o = 16; o > 0; o >>= 1) {
        a0 += __shfl_down_sync(0xffffffffu, a0, o);
        a1 += __shfl_down_sync(0xffffffffu, a1, o);
        a2 += __shfl_down_sync(0xffffffffu, a2, o);
        a3 += __shfl_down_sync(0xffffffffu, a3, o);
    }
    if (lane == 0) { sh[0][wid] = a0; sh[1][wid] = a1; sh[2][wid] = a2; sh[3][wid] = a3; }
    __syncthreads();
    if (tid == 0) {
        float t0 = 0.f, t1 = 0.f, t2 = 0.f, t3 = 0.f;
#pragma unroll
        for (int w = 0; w < 8; w++) { t0 += sh[0][w]; t1 += sh[1][w]; t2 += sh[2][w]; t3 += sh[3][w]; }
        g_part[b][0] = t0; g_part[b][1] = t1; g_part[b][2] = t2; g_part[b][3] = t3;
        __threadfence();
        s_ticket = atomicAdd(&g_ctr, 1u);
    }
    __syncthreads();

    if (s_ticket == NB_COMBINE - 1) {
        __threadfence();
        if (tid < NB_COMBINE) {
            volatile float (*part)[4] = g_part;
            float p0 = part[tid][0], p1 = part[tid][1];
            float p2 = part[tid][2], p3 = part[tid][3];
#pragma unroll
            for (int o = 16; o > 0; o >>= 1) {
                p0 += __shfl_down_sync(0xffffffffu, p0, o);
                p1 += __shfl_down_sync(0xffffffffu, p1, o);
                p2 += __shfl_down_sync(0xffffffffu, p2, o);
                p3 += __shfl_down_sync(0xffffffffu, p3, o);
            }
            if (lane == 0) { sh[0][wid] = p0; sh[1][wid] = p1; sh[2][wid] = p2; sh[3][wid] = p3; }
        }
        __syncthreads();
        if (tid == 0) {
            float s0 = sh[0][0] + sh[0][1];
            float s1 = sh[1][0] + sh[1][1];
            float s2 = sh[2][0] + sh[2][1];
            float s3 = sh[3][0] + sh[3][1];
            out[0] = s0 / fmaxf(s1, 1e-9f) + s2 / fmaxf(s3, 1e-9f);
            g_ctr = 0u;
        }
    }
}

// ---------------------------------------------------------------------------
extern "C" void kernel_launch(void* const* d_in, const int* in_sizes, int n_in,
                              void* d_out, int out_size) {
    const float* pred = (const float*)d_in[0];
    const float* gt   = (const float*)d_in[1];
    const float* wp   = (const float*)d_in[2];
    const float* wg   = (const float*)d_in[3];
    float* out = (float*)d_out;

    k_hist<<<(NP + NG) / 256, 256>>>(pred, gt);
    k_scan<<<2, 1024>>>();
    k_scatter<<<(NP + NG) / 256, 256>>>(pred, gt);
    k_query<<<256, 256>>>();
    k_combine<<<NB_COMBINE, 256>>>(wp, wg, out);
}

// round 13
// speedup vs baseline: 4.9969x; 1.0456x over previous
#include <cuda_runtime.h>
#include <cuda_bf16.h>
#include <cstdint>

#define NP 16384
#define NG 16384
#define NB 2048
#define XMIN (-5.5f)
#define XSPAN 11.0f
#define INV_W ((float)NB / XSPAN)
#define FLT_BIG 3.402823466e38f
#define INF_BITS 0x7f800000u
#define NB_COMBINE 64
#define CHD 12                    // chunks per depth-warp (24/side -> 768 ranks)

// ---------------------------------------------------------------------------
// Device-global scratch. hist_*, g_key_*, g_ctr, g_fb_count must be zero at
// replay start: statically zero-init + re-zeroed by the consuming kernels.
// ---------------------------------------------------------------------------
__device__ int    hist_p[NB], hist_g[NB];
__device__ int    cstart_p[NB + 1], cstart_g[NB + 1];
__device__ int    cursor_p[NB], cursor_g[NB];
__device__ float4 spt[NP], sgt[NG];        // x-sorted (x,y,z,|pt|^2)
__device__ int    orig_p[NP], orig_g[NG];
__device__ unsigned int g_key_pred[NP];    // key = INF_BITS - bits(min d2); 0 == +inf
__device__ unsigned int g_key_gt[NG];
__device__ float  xLa[1024], xRa[1024];    // per query-group window edges
__device__ int    g_fb_list[NP + NG];
__device__ int    g_fb_count;
__device__ float  g_part[NB_COMBINE][4];
__device__ unsigned int g_ctr;

__device__ __forceinline__ int bucket_of(float x) {
    int b = (int)((x - XMIN) * INV_W);
    return min(max(b, 0), NB - 1);
}

// ---------------------------------------------------------------------------
// K1: bucket histograms
// ---------------------------------------------------------------------------
__global__ void k_hist(const float* __restrict__ pp, const float* __restrict__ gp) {
    int i = blockIdx.x * blockDim.x + threadIdx.x;
    if (i < NP) atomicAdd(&hist_p[bucket_of(pp[3 * i])], 1);
    else        atomicAdd(&hist_g[bucket_of(gp[3 * (i - NP)])], 1);
}

// ---------------------------------------------------------------------------
// K2: exclusive scan, one block per cloud; resets hist for next replay.
// ---------------------------------------------------------------------------
__device__ __forceinline__ void scan_one(int* hist, int* cstart, int* cursor, int total) {
    __shared__ int wsum[32];
    const int tid = threadIdx.x, lane = tid & 31, w = tid >> 5;
    int v0 = hist[2 * tid], v1 = hist[2 * tid + 1];
    int s = v0 + v1, incl = s;
#pragma unroll
    for (int o = 1; o < 32; o <<= 1) {
        int n = __shfl_up_sync(0xffffffffu, incl, o);
        if (lane >= o) incl += n;
    }
    if (lane == 31) wsum[w] = incl;
    __syncthreads();
    if (w == 0) {
        int t2 = wsum[lane], inc2 = t2;
#pragma unroll
        for (int o = 1; o < 32; o <<= 1) {
            int n = __shfl_up_sync(0xffffffffu, inc2, o);
            if (lane >= o) inc2 += n;
        }
        wsum[lane] = inc2 - t2;
    }
    __syncthreads();
    int base = wsum[w] + incl - s;
    cstart[2 * tid] = base;       cstart[2 * tid + 1] = base + v0;
    cursor[2 * tid] = base;       cursor[2 * tid + 1] = base + v0;
    hist[2 * tid] = 0;            hist[2 * tid + 1] = 0;
    if (tid == 1023) cstart[NB] = total;
}

__global__ void k_scan() {
    if (blockIdx.x == 0) scan_one(hist_p, cstart_p, cursor_p, NP);
    else                 scan_one(hist_g, cstart_g, cursor_g, NG);
}

// ---------------------------------------------------------------------------
// K3: scatter into x-sorted order (within-bucket order irrelevant: final
// answers are exact NN values either via certification or fallback).
// ---------------------------------------------------------------------------
__global__ void k_scatter(const float* __restrict__ pp, const float* __restrict__ gp) {
    int i = blockIdx.x * blockDim.x + threadIdx.x;
    if (i < NP) {
        float x = pp[3 * i], y = pp[3 * i + 1], z = pp[3 * i + 2];
        int pos = atomicAdd(&cursor_p[bucket_of(x)], 1);
        spt[pos] = make_float4(x, y, z, x * x + y * y + z * z);
        orig_p[pos] = i;
    } else {
        int j = i - NP;
        float x = gp[3 * j], y = gp[3 * j + 1], z = gp[3 * j + 2];
        int pos = atomicAdd(&cursor_g[bucket_of(x)], 1);
        sgt[pos] = make_float4(x, y, z, x * x + y * y + z * z);
        orig_g[pos] = j;
    }
}

// ---------------------------------------------------------------------------
// K4: PURE DENSE windowed NN. 4096 warps; warp gw:
//   side = gw&1 (0 right incl anchor chunk, 1 left), depth = (gw>>1)&1,
//   group = gw>>2 (0..1023), half = group>>9 (0 pred-queries, 1 gt-queries),
//   queries = 32 consecutive sorted slots.
// Each warp processes exactly CHD chunks (no votes, software-pipelined LDG).
// Window per side = 2*CHD*32 = 768 ranks. Depth-1 warps record the outermost
// examined x per group for certification. OOB -> sentinel (x=+-1e30, w=BIG).
// t-space: t = -2 p.g + |g|^2; d2 = t + |p|^2; clamp at end; atomicMax key.
// ---------------------------------------------------------------------------
__global__ __launch_bounds__(256)
void k_query() {
    __shared__ float4 sh[8][2][32];
    const int lane = threadIdx.x & 31;
    const int wl = threadIdx.x >> 5;
    const int gw = blockIdx.x * 8 + wl;           // 0..4095
    const int side  = gw & 1;
    const int depth = (gw >> 1) & 1;
    const int group = gw >> 2;                    // 0..1023
    const int half  = group >> 9;                 // 0: pred queries, 1: gt
    const int q = (group & 511) * 32 + lane;

    const float4* __restrict__ T  = half ? spt : sgt;
    const int*    __restrict__ cs = half ? cstart_p : cstart_g;
    const float4 p = half ? sgt[q] : spt[q];
    const float px = p.x, pq = p.w;
    const float qx = -2.0f * p.x, qy = -2.0f * p.y, qz = -2.0f * p.z;

    const float px0 = __shfl_sync(0xffffffffu, px, 0);
    const int anchor = cs[bucket_of(px0)];
    const int step  = side ? -32 : 32;
    const int base0 = side ? (anchor - 32 * (depth * CHD + 1))
                           : (anchor + 32 * (depth * CHD));
    const float sentx = side ? -1e30f : 1e30f;

    float b0 = FLT_BIG, b1 = FLT_BIG, b2 = FLT_BIG, b3 = FLT_BIG;

    // prefetch chunk 0
    float4 nxt, last;
    {
        int idx = base0 + lane;
        nxt = (idx >= 0 && idx < NG) ? T[idx] : make_float4(sentx, 0.f, 0.f, FLT_BIG);
    }
#pragma unroll
    for (int c = 0; c < CHD; c++) {
        float4 cur = nxt;
        last = cur;
        if (c + 1 < CHD) {
            int idx = base0 + step * (c + 1) + lane;
            nxt = (idx >= 0 && idx < NG) ? T[idx] : make_float4(sentx, 0.f, 0.f, FLT_BIG);
        }
        sh[wl][c & 1][lane] = cur;
        __syncwarp();
#pragma unroll
        for (int k = 0; k < 32; k += 4) {
            float4 c0 = sh[wl][c & 1][k + 0];
            float4 c1 = sh[wl][c & 1][k + 1];
            float4 c2 = sh[wl][c & 1][k + 2];
            float4 c3 = sh[wl][c & 1][k + 3];
            float t0 = fmaf(qx, c0.x, fmaf(qy, c0.y, fmaf(qz, c0.z, c0.w)));
            float t1 = fmaf(qx, c1.x, fmaf(qy, c1.y, fmaf(qz, c1.z, c1.w)));
            float t2 = fmaf(qx, c2.x, fmaf(qy, c2.y, fmaf(qz, c2.z, c2.w)));
            float t3 = fmaf(qx, c3.x, fmaf(qy, c3.y, fmaf(qz, c3.z, c3.w)));
            b0 = fminf(b0, t0); b1 = fminf(b1, t1);
            b2 = fminf(b2, t2); b3 = fminf(b3, t3);
        }
        __syncwarp();
    }

    float best = fmaxf(fminf(fminf(b0, b1), fminf(b2, b3)) + pq, 0.0f);
    unsigned key = INF_BITS - __float_as_uint(best);
    if (half) atomicMax(&g_key_gt[orig_g[q]], key);
    else      atomicMax(&g_key_pred[orig_p[q]], key);

    // depth-1 warps record the outermost examined x (sentinel if window hit
    // the array end -> certification auto-passes on that side, correctly,
    // because no unexamined candidates remain there).
    if (depth == 1) {
        float xe = __shfl_sync(0xffffffffu, last.x, side ? 0 : 31);
        if (lane == 0) {
            if (side) xLa[group] = xe;
            else      xRa[group] = xe;
        }
    }
}

// ---------------------------------------------------------------------------
// K5: certification. A query is exact iff no unexamined candidate can beat
// its combined best: dxL^2 >= best && dxR^2 >= best. Uncertified queries are
// warp-ballot compacted into g_fb_list.
// ---------------------------------------------------------------------------
__global__ void k_verify() {
    int i = blockIdx.x * blockDim.x + threadIdx.x;   // 0..32767
    int half = i >> 14;
    int q = i & 16383;
    float4 p = half ? sgt[q] : spt[q];
    int oi = half ? orig_g[q] : orig_p[q];
    unsigned key = half ? g_key_gt[oi] : g_key_pred[oi];
    float best = __uint_as_float(INF_BITS - key);
    int grp = (half << 9) | (q >> 5);
    float dl = fmaxf(p.x - xLa[grp], 0.0f);
    float dr = fmaxf(xRa[grp] - p.x, 0.0f);
    bool bad = !((dl * dl >= best) && (dr * dr >= best));

    unsigned bal = __ballot_sync(0xffffffffu, bad);
    int cnt = __popc(bal);
    if (cnt) {
        int basepos = 0;
        if ((threadIdx.x & 31) == 0) basepos = atomicAdd(&g_fb_count, cnt);
        basepos = __shfl_sync(0xffffffffu, basepos, 0);
        if (bad) {
            int off = __popc(bal & ((1u << (threadIdx.x & 31)) - 1u));
            g_fb_list[basepos + off] = i;
        }
    }
}

// ---------------------------------------------------------------------------
// K6: exact fallback for uncertified queries (expected ~tens). 8 warps per
// query, each warp scans a 2048-rank slice; lanes stride the slice (coalesced
// LDG.128, unrolled for MLP); warp-min then atomicMax key.
// ---------------------------------------------------------------------------
__global__ __launch_bounds__(256)
void k_fallback() {
    const int lane = threadIdx.x & 31;
    const int warp = (blockIdx.x * blockDim.x + threadIdx.x) >> 5;
    const int nwarps = (gridDim.x * blockDim.x) >> 5;
    const int ntask = g_fb_count * 8;

    for (int t = warp; t < ntask; t += nwarps) {
        int e = g_fb_list[t >> 3];
        int part = t & 7;
        int half = e >> 14;
        int q = e & 16383;
        const float4* __restrict__ T = half ? spt : sgt;
        float4 p = half ? sgt[q] : spt[q];
        float qx = -2.0f * p.x, qy = -2.0f * p.y, qz = -2.0f * p.z, pq = p.w;
        int s = part * 2048;

        float b0 = FLT_BIG, b1 = FLT_BIG, b2 = FLT_BIG, b3 = FLT_BIG;
#pragma unroll 4
        for (int r = 0; r < 2048; r += 128) {
            float4 c0 = T[s + r + lane];
            float4 c1 = T[s + r + 32 + lane];
            float4 c2 = T[s + r + 64 + lane];
            float4 c3 = T[s + r + 96 + lane];
            float t0 = fmaf(qx, c0.x, fmaf(qy, c0.y, fmaf(qz, c0.z, c0.w)));
            float t1 = fmaf(qx, c1.x, fmaf(qy, c1.y, fmaf(qz, c1.z, c1.w)));
            float t2 = fmaf(qx, c2.x, fmaf(qy, c2.y, fmaf(qz, c2.z, c2.w)));
            float t3 = fmaf(qx, c3.x, fmaf(qy, c3.y, fmaf(qz, c3.z, c3.w)));
            b0 = fminf(b0, t0); b1 = fminf(b1, t1);
            b2 = fminf(b2, t2); b3 = fminf(b3, t3);
        }
        float b = fminf(fminf(b0, b1), fminf(b2, b3));
#pragma unroll
        for (int o = 16; o > 0; o >>= 1)
            b = fminf(b, __shfl_xor_sync(0xffffffffu, b, o));
        if (lane == 0) {
            float best = fmaxf(b + pq, 0.0f);
            unsigned key = INF_BITS - __float_as_uint(best);
            int oi = half ? orig_g[q] : orig_p[q];
            if (half) atomicMax(&g_key_gt[oi], key);
            else      atomicMax(&g_key_pred[oi], key);
        }
    }
}

// ---------------------------------------------------------------------------
// K7: weighted partial sums + last-block final combine (deterministic
// fixed-order sums over original indices). Resets keys/counters for replay.
// ---------------------------------------------------------------------------
__global__ __launch_bounds__(256, 1)
void k_combine(const float* __restrict__ wp, const float* __restrict__ wg,
               float* __restrict__ out) {
    __shared__ float sh[4][8];
    __shared__ unsigned int s_ticket;
    const int b = blockIdx.x, tid = threadIdx.x;
    const int lane = tid & 31, wid = tid >> 5;
    const int i = b * 256 + tid;

    unsigned kp = g_key_pred[i];
    unsigned kg = g_key_gt[i];
    g_key_pred[i] = 0u;
    g_key_gt[i]   = 0u;
    float mp = __uint_as_float(INF_BITS - kp);
    float mg = __uint_as_float(INF_BITS - kg);
    float w1 = wp[i], w2 = wg[i];
    float a0 = w1 * mp, a1 = w1, a2 = w2 * mg, a3 = w2;
#pragma unroll
    for (int o = 16; o > 0; o >>= 1) {
        a0 += __shfl_down_sync(0xffffffffu, a0, o);
        a1 += __shfl_down_sync(0xffffffffu, a1, o);
        a2 += __shfl_down_sync(0xffffffffu, a2, o);
        a3 += __shfl_down_sync(0xffffffffu, a3, o);
    }
    if (lane == 0) { sh[0][wid] = a0; sh[1][wid] = a1; sh[2][wid] = a2; sh[3][wid] = a3; }
    __syncthreads();
    if (tid == 0) {
        float t0 = 0.f, t1 = 0.f, t2 = 0.f, t3 = 0.f;
#pragma unroll
        for (int w = 0; w < 8; w++) { t0 += sh[0][w]; t1 += sh[1][w]; t2 += sh[2][w]; t3 += sh[3][w]; }
        g_part[b][0] = t0; g_part[b][1] = t1; g_part[b][2] = t2; g_part[b][3] = t3;
        __threadfence();
        s_ticket = atomicAdd(&g_ctr, 1u);
    }
    __syncthreads();

    if (s_ticket == NB_COMBINE - 1) {
        __threadfence();
        if (tid < NB_COMBINE) {
            volatile float (*part)[4] = g_part;
            float p0 = part[tid][0], p1 = part[tid][1];
            float p2 = part[tid][2], p3 = part[tid][3];
#pragma unroll
            for (int o = 16; o > 0; o >>= 1) {
                p0 += __shfl_down_sync(0xffffffffu, p0, o);
                p1 += __shfl_down_sync(0xffffffffu, p1, o);
                p2 += __shfl_down_sync(0xffffffffu, p2, o);
                p3 += __shfl_down_sync(0xffffffffu, p3, o);
            }
            if (lane == 0) { sh[0][wid] = p0; sh[1][wid] = p1; sh[2][wid] = p2; sh[3][wid] = p3; }
        }
        __syncthreads();
        if (tid == 0) {
            float s0 = sh[0][0] + sh[0][1];
            float s1 = sh[1][0] + sh[1][1];
            float s2 = sh[2][0] + sh[2][1];
            float s3 = sh[3][0] + sh[3][1];
            out[0] = s0 / fmaxf(s1, 1e-9f) + s2 / fmaxf(s3, 1e-9f);
            g_ctr = 0u;
            g_fb_count = 0;
        }
    }
}

// ---------------------------------------------------------------------------
extern "C" void kernel_launch(void* const* d_in, const int* in_sizes, int n_in,
                              void* d_out, int out_size) {
    const float* pred = (const float*)d_in[0];
    const float* gt   = (const float*)d_in[1];
    const float* wp   = (const float*)d_in[2];
    const float* wg   = (const float*)d_in[3];
    float* out = (float*)d_out;

    k_hist<<<(NP + NG) / 256, 256>>>(pred, gt);
    k_scan<<<2, 1024>>>();
    k_scatter<<<(NP + NG) / 256, 256>>>(pred, gt);
    k_query<<<512, 256>>>();
    k_verify<<<128, 256>>>();
    k_fallback<<<128, 256>>>();
    k_combine<<<NB_COMBINE, 256>>>(wp, wg, out);
}